// round 10
// baseline (speedup 1.0000x reference)
#include <cuda_runtime.h>
#include <cfloat>
#include <cstddef>
#include <cstdint>

// Problem constants
#define BB     2
#define TQ     1024
#define TMEMN  1024
#define TK     2048
#define IN_DIM 1024
#define HH     16
#define DD     64
#define HD     1024
#define LD2    2048

// ---------------------------------------------------------------------------
// Scratch
// ---------------------------------------------------------------------------
__device__ float g_XM  [BB * TK * IN_DIM];           // [b][ mem ; x ][1024] rounded
__device__ float g_Wqpt[LD2 * IN_DIM];               // [Wq|Wpos]^T rounded
__device__ float g_Wkvt[LD2 * IN_DIM];               // [Wk|Wv]^T rounded
__device__ float g_Wot [HD * HD];                    // Wout^T rounded
__device__ float g_QP  [BB * TQ * LD2];              // [Q | POS] rounded
__device__ float g_KV  [BB * TK * LD2];              // [K | V]   rounded
__device__ float g_S2  [(size_t)BB * HH * TQ * TQ];  // Q·POS^T (fp32)
__device__ float g_PB  [BB * HH * TQ];               // v2·POS^T (fp32)
__device__ float g_CTX [BB * TQ * HD];               // attn @ V (rounded)

// ---------------------------------------------------------------------------
// Helpers
// ---------------------------------------------------------------------------
__device__ __forceinline__ uint32_t f2tf(float f) {
    uint32_t r;
    asm("cvt.rna.tf32.f32 %0, %1;" : "=r"(r) : "f"(f));
    return r;
}
__device__ __forceinline__ float rndf(float f) { return __uint_as_float(f2tf(f)); }

__device__ __forceinline__ void mma8(float* d, const uint32_t* a, const uint32_t* b) {
    asm volatile(
        "mma.sync.aligned.m16n8k8.row.col.f32.tf32.tf32.f32 "
        "{%0,%1,%2,%3},{%4,%5,%6,%7},{%8,%9},{%0,%1,%2,%3};"
        : "+f"(d[0]), "+f"(d[1]), "+f"(d[2]), "+f"(d[3])
        : "r"(a[0]), "r"(a[1]), "r"(a[2]), "r"(a[3]), "r"(b[0]), "r"(b[1]));
}

__device__ __forceinline__ void cpa16(float* s, const float* g) {
    uint32_t sa = (uint32_t)__cvta_generic_to_shared(s);
    asm volatile("cp.async.cg.shared.global [%0], [%1], 16;" :: "r"(sa), "l"(g));
}

// ---------------------------------------------------------------------------
// gemm2: C[128,128]-tiled  C = A[M,K] · B[N,K]^T  (both K-major, pre-rounded)
// 4 warps, warp tile 64x64, K-tile 32, 3-stage cp.async pipeline.
// ---------------------------------------------------------------------------
#define G2_AST   36
#define G2_STG   (128 * G2_AST)
#define G2_SMEM  (6 * G2_STG * 4)      // 110592 bytes

template <bool RND>
__global__ __launch_bounds__(128)
void gemm2(const float* __restrict__ A, const float* __restrict__ B,
           float* __restrict__ C, int lda, int ldb, int ldc, int K, int Hdim,
           long long sAb, long long sAh, long long sBb, long long sBh,
           long long sCb, long long sCh)
{
    extern __shared__ float sg[];
    float* const Asm = sg;
    float* const Bsm = sg + 3 * G2_STG;

    const int z = blockIdx.z;
    const int b = z / Hdim;
    const int h = z - b * Hdim;
    A += b * sAb + h * sAh;
    B += b * sBb + h * sBh;
    C += b * sCb + h * sCh;

    const int m0 = blockIdx.y * 128;
    const int n0 = blockIdx.x * 128;
    const int tid  = threadIdx.x;
    const int warp = tid >> 5;
    const int lane = tid & 31;
    const int lg = lane >> 2;
    const int lc = lane & 3;
    const int wR = (warp & 1) * 64;
    const int wC = (warp >> 1) * 64;

    float acc[4][8][4];
#pragma unroll
    for (int mt = 0; mt < 4; mt++)
#pragma unroll
        for (int nt = 0; nt < 8; nt++)
#pragma unroll
            for (int i = 0; i < 4; i++) acc[mt][nt][i] = 0.f;

    const int nc = K >> 5;

    auto loadStage = [&](int s, int c) {
        const int k0 = c << 5;
        float* as = Asm + s * G2_STG;
        float* bs = Bsm + s * G2_STG;
#pragma unroll
        for (int t = 0; t < 8; t++) {
            int idx = tid + t * 128;
            int r = idx >> 3, ch = (idx & 7) * 4;
            cpa16(&as[r * G2_AST + ch], A + (size_t)(m0 + r) * lda + k0 + ch);
            cpa16(&bs[r * G2_AST + ch], B + (size_t)(n0 + r) * ldb + k0 + ch);
        }
        asm volatile("cp.async.commit_group;");
    };

    loadStage(0, 0);
    if (nc > 1) loadStage(1, 1);

    for (int c = 0; c < nc; c++) {
        if (c + 1 < nc) asm volatile("cp.async.wait_group 1;");
        else            asm volatile("cp.async.wait_group 0;");
        __syncthreads();
        if (c + 2 < nc) loadStage((c + 2) % 3, c + 2);

        const float* as = Asm + (c % 3) * G2_STG;
        const float* bs = Bsm + (c % 3) * G2_STG;
#pragma unroll
        for (int koff = 0; koff < 32; koff += 8) {
            uint32_t af[4][4];
#pragma unroll
            for (int mt = 0; mt < 4; mt++) {
                const int r = wR + mt * 16 + lg;
                af[mt][0] = __float_as_uint(as[r * G2_AST + koff + lc]);
                af[mt][1] = __float_as_uint(as[(r + 8) * G2_AST + koff + lc]);
                af[mt][2] = __float_as_uint(as[r * G2_AST + koff + 4 + lc]);
                af[mt][3] = __float_as_uint(as[(r + 8) * G2_AST + koff + 4 + lc]);
            }
            uint32_t bf[8][2];
#pragma unroll
            for (int nt = 0; nt < 8; nt++) {
                const int cc = wC + nt * 8 + lg;
                bf[nt][0] = __float_as_uint(bs[cc * G2_AST + koff + lc]);
                bf[nt][1] = __float_as_uint(bs[cc * G2_AST + koff + 4 + lc]);
            }
#pragma unroll
            for (int mt = 0; mt < 4; mt++)
#pragma unroll
                for (int nt = 0; nt < 8; nt++)
                    mma8(acc[mt][nt], af[mt], bf[nt]);
        }
    }

#pragma unroll
    for (int mt = 0; mt < 4; mt++) {
        const int r = m0 + wR + mt * 16 + lg;
#pragma unroll
        for (int nt = 0; nt < 8; nt++) {
            const int cc = n0 + wC + nt * 8 + 2 * lc;
            float v0 = acc[mt][nt][0], v1 = acc[mt][nt][1];
            float v2 = acc[mt][nt][2], v3 = acc[mt][nt][3];
            if (RND) { v0 = rndf(v0); v1 = rndf(v1); v2 = rndf(v2); v3 = rndf(v3); }
            *reinterpret_cast<float2*>(&C[(size_t)r * ldc + cc])       = make_float2(v0, v1);
            *reinterpret_cast<float2*>(&C[(size_t)(r + 8) * ldc + cc]) = make_float2(v2, v3);
        }
    }
}

// ---------------------------------------------------------------------------
// Prep kernels
// ---------------------------------------------------------------------------
__global__ void round_concat(float* __restrict__ dst, const float* __restrict__ x,
                             const float* __restrict__ mem)
{
    int i = blockIdx.x * blockDim.x + threadIdx.x;
    if (i >= BB * TK * IN_DIM / 4) return;
    int row = i >> 8;
    int c4  = i & 255;
    int b = row >> 11, r = row & 2047;
    const float4* src = (r < 1024)
        ? reinterpret_cast<const float4*>(mem) + ((size_t)b * 1024 + r) * 256 + c4
        : reinterpret_cast<const float4*>(x)   + ((size_t)b * 1024 + (r - 1024)) * 256 + c4;
    float4 v = *src;
    v.x = rndf(v.x); v.y = rndf(v.y); v.z = rndf(v.z); v.w = rndf(v.w);
    reinterpret_cast<float4*>(dst)[i] = v;
}

// One launch for all three weight transposes.
// z=0: Wqpt <- [Wq|Wpos], z=1: Wkvt <- [Wk|Wv], z=2: Wot <- Wout (x-blocks 0..31)
__global__ void transpose_round_all(float* __restrict__ dqp, float* __restrict__ dkv,
                                    float* __restrict__ dwo,
                                    const float* __restrict__ Wq, const float* __restrict__ Wpos,
                                    const float* __restrict__ Wk, const float* __restrict__ Wv,
                                    const float* __restrict__ Wout)
{
    __shared__ float t[32][33];
    const int zz = blockIdx.z;
    float* dst;
    const float* s0;
    const float* s1;
    if (zz == 0)      { dst = dqp; s0 = Wq;   s1 = Wpos; }
    else if (zz == 1) { dst = dkv; s0 = Wk;   s1 = Wv;   }
    else              { dst = dwo; s0 = Wout; s1 = Wout; if (blockIdx.x >= 32) return; }

    const int n0 = blockIdx.x * 32;
    const int k0 = blockIdx.y * 32;
    const float* src = (n0 < 1024) ? s0 : s1;
    const int nn = (n0 < 1024) ? n0 : n0 - 1024;
    const int tx = threadIdx.x, ty = threadIdx.y;
#pragma unroll
    for (int i = 0; i < 32; i += 8)
        t[ty + i][tx] = rndf(src[(size_t)(k0 + ty + i) * 1024 + nn + tx]);
    __syncthreads();
#pragma unroll
    for (int i = 0; i < 32; i += 8)
        dst[(size_t)(n0 + ty + i) * 1024 + k0 + tx] = t[tx][ty + i];
}

// PB[b*16+h][n] = v2[h] . POS[b,n,h,:]
__global__ void pb_kernel(const float* __restrict__ QP, const float* __restrict__ v2,
                          float* __restrict__ PB)
{
    int idx = blockIdx.x * 256 + threadIdx.x;
    int z = idx >> 10, n = idx & 1023;
    int b = z >> 4, h = z & 15;
    const float* pos = QP + ((size_t)(b * TQ + n)) * LD2 + 1024 + h * DD;
    const float* vv  = v2 + h * DD;
    float s = 0.f;
#pragma unroll
    for (int k = 0; k < DD; k++) s += vv[k] * pos[k];
    PB[idx] = s;
}

// ---------------------------------------------------------------------------
// Flash attention (verbatim from passing R9 kernel)
// ---------------------------------------------------------------------------
#define KSTR 68
#define VSTR 72
#define PSTR 132
#define SM_K0 0
#define SM_K1 (128 * KSTR)
#define SM_V0 (2 * 128 * KSTR)
#define SM_V1 (2 * 128 * KSTR + 128 * VSTR)
#define SM_P  (2 * 128 * KSTR + 2 * 128 * VSTR)
#define SM_TOT (SM_P + 128 * PSTR)
#define FLASH_SMEM (SM_TOT * 4)

__device__ __forceinline__ float posval(const float* __restrict__ Pr,
                                        const float* __restrict__ PBh, int q, int j) {
    if (j < 0 || j == q) return 0.f;
    int qq, cc;
    if (j < q) { qq = q;     cc = TQ + j - q; }
    else       { qq = q + 1; cc = j - q - 1;  }
    return __ldg(Pr + (size_t)qq * TQ + cc) + __ldg(PBh + cc);
}

__global__ __launch_bounds__(256, 1)
void flash_attn(const float* __restrict__ QP, const float* __restrict__ KV,
                const float* __restrict__ S2, const float* __restrict__ PB,
                const float* __restrict__ u, float* __restrict__ CTX)
{
    extern __shared__ float sm[];
    float* const Kbuf[2] = { sm + SM_K0, sm + SM_K1 };
    float* const Vbuf[2] = { sm + SM_V0, sm + SM_V1 };
    float* const Pb = sm + SM_P;

    const int q0 = blockIdx.x * 128;
    const int h  = blockIdx.y;
    const int b  = blockIdx.z;
    const int tid = threadIdx.x;
    const int w   = tid >> 5;
    const int lane = tid & 31;
    const int lg = lane >> 2;
    const int lc = lane & 3;

    const float* Qb = QP + ((size_t)b * TQ) * LD2 + h * DD;
    const float* Kb = KV + ((size_t)b * TK) * LD2 + h * DD;
    const float* Vb = Kb + 1024;
    const float* Pr = S2 + ((size_t)(b * HH + h)) * TQ * TQ;
    const float* PBh = PB + (size_t)(b * HH + h) * TQ;

#pragma unroll
    for (int i = 0; i < 8; i++) {
        int lin = tid + 256 * i;
        int r = lin >> 4, c4 = (lin & 15) * 4;
        float4 qv = *reinterpret_cast<const float4*>(Qb + (size_t)(q0 + r) * LD2 + c4);
        float4 uv = *reinterpret_cast<const float4*>(u + h * DD + c4);
        float* d = &Pb[r * PSTR + c4];
        d[0] = rndf(qv.x + uv.x); d[1] = rndf(qv.y + uv.y);
        d[2] = rndf(qv.z + uv.z); d[3] = rndf(qv.w + uv.w);
    }
    __syncthreads();

    uint32_t qf[8][4];
    {
        const int r0 = w * 16 + lg, r1 = r0 + 8;
#pragma unroll
        for (int s = 0; s < 8; s++) {
            qf[s][0] = __float_as_uint(Pb[r0 * PSTR + 8 * s + lc]);
            qf[s][1] = __float_as_uint(Pb[r1 * PSTR + 8 * s + lc]);
            qf[s][2] = __float_as_uint(Pb[r0 * PSTR + 8 * s + 4 + lc]);
            qf[s][3] = __float_as_uint(Pb[r1 * PSTR + 8 * s + 4 + lc]);
        }
    }
    __syncthreads();

    float Oa[8][4];
#pragma unroll
    for (int vt = 0; vt < 8; vt++)
#pragma unroll
        for (int i = 0; i < 4; i++) Oa[vt][i] = 0.f;
    float m0 = -3.0e38f, m1 = -3.0e38f, l0 = 0.f, l1 = 0.f;

    const int gq0 = q0 + w * 16 + lg;

    auto loadChunk = [&](int buf, int c) {
        const float* Kc = Kb + (size_t)c * 128 * LD2;
        const float* Vc = Vb + (size_t)c * 128 * LD2;
#pragma unroll
        for (int i = 0; i < 8; i++) {
            int lin = tid + 256 * i;
            int r = lin >> 4, c4 = (lin & 15) * 4;
            cpa16(&Kbuf[buf][r * KSTR + c4], Kc + (size_t)r * LD2 + c4);
            cpa16(&Vbuf[buf][r * VSTR + c4], Vc + (size_t)r * LD2 + c4);
        }
    };

    loadChunk(0, 0);
    asm volatile("cp.async.commit_group;");
    int buf = 0;

    for (int c = 0; c < 16; c++) {
        if (c < 15) {
            loadChunk(buf ^ 1, c + 1);
            asm volatile("cp.async.commit_group;");
            asm volatile("cp.async.wait_group 1;");
        } else {
            asm volatile("cp.async.wait_group 0;");
        }
        __syncthreads();

        float Sa[16][4];
#pragma unroll
        for (int nt = 0; nt < 16; nt++)
#pragma unroll
            for (int i = 0; i < 4; i++) Sa[nt][i] = 0.f;

        const float* Ks = Kbuf[buf];
        const int kbBase = lg * KSTR + lc;
#pragma unroll
        for (int s = 0; s < 8; s++) {
#pragma unroll
            for (int nt = 0; nt < 16; nt++) {
                uint32_t kb[2];
                kb[0] = __float_as_uint(Ks[kbBase + nt * 8 * KSTR + 8 * s]);
                kb[1] = __float_as_uint(Ks[kbBase + nt * 8 * KSTR + 8 * s + 4]);
                mma8(Sa[nt], qf[s], kb);
            }
        }

        const int kbase = c * 128;
        float rm0 = -3.0e38f, rm1 = -3.0e38f;
#pragma unroll
        for (int nt = 0; nt < 16; nt++) {
            if (kbase >= TMEMN) {
                const int kk0 = kbase + nt * 8 + 2 * lc;
                const int j0 = kk0 - TMEMN, j1 = j0 + 1;
                Sa[nt][0] += posval(Pr, PBh, gq0, j0);
                Sa[nt][1] += posval(Pr, PBh, gq0, j1);
                Sa[nt][2] += posval(Pr, PBh, gq0 + 8, j0);
                Sa[nt][3] += posval(Pr, PBh, gq0 + 8, j1);
            }
            Sa[nt][0] *= 0.125f; Sa[nt][1] *= 0.125f;
            Sa[nt][2] *= 0.125f; Sa[nt][3] *= 0.125f;
            rm0 = fmaxf(rm0, fmaxf(Sa[nt][0], Sa[nt][1]));
            rm1 = fmaxf(rm1, fmaxf(Sa[nt][2], Sa[nt][3]));
        }
        rm0 = fmaxf(rm0, __shfl_xor_sync(0xffffffffu, rm0, 1));
        rm0 = fmaxf(rm0, __shfl_xor_sync(0xffffffffu, rm0, 2));
        rm1 = fmaxf(rm1, __shfl_xor_sync(0xffffffffu, rm1, 1));
        rm1 = fmaxf(rm1, __shfl_xor_sync(0xffffffffu, rm1, 2));

        const float nm0 = fmaxf(m0, rm0), nm1 = fmaxf(m1, rm1);
        const float sc0 = __expf(m0 - nm0), sc1 = __expf(m1 - nm1);
        m0 = nm0; m1 = nm1;

        __syncwarp();
        float rs0 = 0.f, rs1 = 0.f;
        {
            float* p0row = &Pb[(w * 16 + lg) * PSTR];
            float* p1row = p0row + 8 * PSTR;
#pragma unroll
            for (int nt = 0; nt < 16; nt++) {
                float p0 = __expf(Sa[nt][0] - m0);
                float p1 = __expf(Sa[nt][1] - m0);
                float p2 = __expf(Sa[nt][2] - m1);
                float p3 = __expf(Sa[nt][3] - m1);
                rs0 += p0 + p1; rs1 += p2 + p3;
                *reinterpret_cast<float2*>(p0row + nt * 8 + 2 * lc) =
                    make_float2(rndf(p0), rndf(p1));
                *reinterpret_cast<float2*>(p1row + nt * 8 + 2 * lc) =
                    make_float2(rndf(p2), rndf(p3));
            }
        }
        rs0 += __shfl_xor_sync(0xffffffffu, rs0, 1);
        rs0 += __shfl_xor_sync(0xffffffffu, rs0, 2);
        rs1 += __shfl_xor_sync(0xffffffffu, rs1, 1);
        rs1 += __shfl_xor_sync(0xffffffffu, rs1, 2);
        l0 = l0 * sc0 + rs0;
        l1 = l1 * sc1 + rs1;
#pragma unroll
        for (int vt = 0; vt < 8; vt++) {
            Oa[vt][0] *= sc0; Oa[vt][1] *= sc0;
            Oa[vt][2] *= sc1; Oa[vt][3] *= sc1;
        }
        __syncwarp();

        const float* Vs = Vbuf[buf];
        const int pA0 = (w * 16 + lg) * PSTR + lc;
        const int pA1 = pA0 + 8 * PSTR;
#pragma unroll
        for (int s = 0; s < 16; s++) {
            uint32_t af[4];
            af[0] = __float_as_uint(Pb[pA0 + 8 * s]);
            af[1] = __float_as_uint(Pb[pA1 + 8 * s]);
            af[2] = __float_as_uint(Pb[pA0 + 8 * s + 4]);
            af[3] = __float_as_uint(Pb[pA1 + 8 * s + 4]);
            const int vb = (8 * s + lc) * VSTR + lg;
#pragma unroll
            for (int vt = 0; vt < 8; vt++) {
                uint32_t bv[2];
                bv[0] = __float_as_uint(Vs[vb + vt * 8]);
                bv[1] = __float_as_uint(Vs[vb + 4 * VSTR + vt * 8]);
                mma8(Oa[vt], af, bv);
            }
        }
        buf ^= 1;
        __syncthreads();
    }

    const float i0 = 1.f / l0, i1 = 1.f / l1;
    float* C0 = CTX + ((size_t)(b * TQ + gq0)) * HD + h * DD;
    float* C1 = C0 + 8 * HD;
#pragma unroll
    for (int vt = 0; vt < 8; vt++) {
        const int cc = vt * 8 + 2 * lc;
        *reinterpret_cast<float2*>(C0 + cc) =
            make_float2(rndf(Oa[vt][0] * i0), rndf(Oa[vt][1] * i0));
        *reinterpret_cast<float2*>(C1 + cc) =
            make_float2(rndf(Oa[vt][2] * i1), rndf(Oa[vt][3] * i1));
    }
}

// ---------------------------------------------------------------------------
// Host
// ---------------------------------------------------------------------------
extern "C" void kernel_launch(void* const* d_in, const int* in_sizes, int n_in,
                              void* d_out, int out_size)
{
    const float* x    = (const float*)d_in[0];
    const float* mem  = (const float*)d_in[1];
    // d_in[2] = attn_mask (identically True; unused)
    const float* Wq   = (const float*)d_in[3];
    const float* Wk   = (const float*)d_in[4];
    const float* Wv   = (const float*)d_in[5];
    const float* Wpos = (const float*)d_in[6];
    const float* u    = (const float*)d_in[7];
    const float* v2   = (const float*)d_in[8];
    const float* Wout = (const float*)d_in[9];
    float* out = (float*)d_out;

    float *pXM, *pWqpt, *pWkvt, *pWot, *pQP, *pKV, *pS2, *pPB, *pCTX;
    cudaGetSymbolAddress((void**)&pXM,   g_XM);
    cudaGetSymbolAddress((void**)&pWqpt, g_Wqpt);
    cudaGetSymbolAddress((void**)&pWkvt, g_Wkvt);
    cudaGetSymbolAddress((void**)&pWot,  g_Wot);
    cudaGetSymbolAddress((void**)&pQP,   g_QP);
    cudaGetSymbolAddress((void**)&pKV,   g_KV);
    cudaGetSymbolAddress((void**)&pS2,   g_S2);
    cudaGetSymbolAddress((void**)&pPB,   g_PB);
    cudaGetSymbolAddress((void**)&pCTX,  g_CTX);

    cudaFuncSetAttribute(flash_attn, cudaFuncAttributeMaxDynamicSharedMemorySize, FLASH_SMEM);
    cudaFuncSetAttribute(gemm2<true>,  cudaFuncAttributeMaxDynamicSharedMemorySize, G2_SMEM);
    cudaFuncSetAttribute(gemm2<false>, cudaFuncAttributeMaxDynamicSharedMemorySize, G2_SMEM);

    const long long sXMb = (long long)TK * IN_DIM;
    const long long sQPb = (long long)TQ * LD2;
    const long long sKVb = (long long)TK * LD2;

    // launch 0: input concat+round
    {
        int n4 = BB * TK * IN_DIM / 4;
        round_concat<<<(n4 + 255) / 256, 256>>>(pXM, x, mem);
    }
    // launch 1: all weight transposes in one kernel
    transpose_round_all<<<dim3(64, 32, 3), dim3(32, 8)>>>(
        pWqpt, pWkvt, pWot, Wq, Wpos, Wk, Wv, Wout);

    // launches 2 & 3: projection GEMMs (profiler-steered: one of these is captured)
    gemm2<true><<<dim3(16, 8, 2), 128, G2_SMEM>>>(
        pXM + (size_t)TMEMN * IN_DIM, pWqpt, pQP,
        IN_DIM, IN_DIM, LD2, IN_DIM, 1,
        sXMb, 0, 0, 0, sQPb, 0);
    gemm2<true><<<dim3(16, 16, 2), 128, G2_SMEM>>>(
        pXM, pWkvt, pKV,
        IN_DIM, IN_DIM, LD2, IN_DIM, 1,
        sXMb, 0, 0, 0, sKVb, 0);

    // S2 = Q · POS^T (per b,h; K=64)
    gemm2<false><<<dim3(8, 8, 32), 128, G2_SMEM>>>(
        pQP, pQP + 1024, pS2,
        LD2, LD2, TQ, DD, HH,
        sQPb, DD, sQPb, DD,
        (long long)HH * TQ * TQ, (long long)TQ * TQ);

    // PB = v2 · POS^T
    pb_kernel<<<128, 256>>>(pQP, v2, pPB);

    // flash attention
    flash_attn<<<dim3(8, 16, 2), 256, FLASH_SMEM>>>(pQP, pKV, pS2, pPB, u, pCTX);

    // OUT = CTX · Wout^T
    gemm2<false><<<dim3(8, 16, 1), 128, G2_SMEM>>>(
        pCTX, pWot, out,
        HD, HD, HD, HD, 1,
        0, 0, 0, 0, 0, 0);
}

// round 11
// speedup vs baseline: 1.0154x; 1.0154x over previous
#include <cuda_runtime.h>
#include <cfloat>
#include <cstddef>
#include <cstdint>

// Problem constants
#define BB     2
#define TQ     1024
#define TMEMN  1024
#define TK     2048
#define IN_DIM 1024
#define HH     16
#define DD     64
#define HD     1024
#define LD2    2048

// ---------------------------------------------------------------------------
// Scratch
// ---------------------------------------------------------------------------
__device__ float g_XM  [BB * TK * IN_DIM];           // [b][ mem ; x ][1024] rounded
__device__ float g_Wqpt[LD2 * IN_DIM];               // [Wq|Wpos]^T rounded
__device__ float g_Wkvt[LD2 * IN_DIM];               // [Wk|Wv]^T rounded
__device__ float g_Wot [HD * HD];                    // Wout^T rounded
__device__ float g_QP  [BB * TQ * LD2];              // [Q | POS] rounded
__device__ float g_KV  [BB * TK * LD2];              // [K | V]   rounded
__device__ float g_S2  [(size_t)BB * HH * TQ * TQ];  // Q·POS^T (fp32)
__device__ float g_PB  [BB * HH * TQ];               // v2·POS^T (fp32)
__device__ float g_CTX [BB * TQ * HD];               // attn @ V (rounded)

// ---------------------------------------------------------------------------
// Helpers
// ---------------------------------------------------------------------------
__device__ __forceinline__ uint32_t f2tf(float f) {
    uint32_t r;
    asm("cvt.rna.tf32.f32 %0, %1;" : "=r"(r) : "f"(f));
    return r;
}
__device__ __forceinline__ float rndf(float f) { return __uint_as_float(f2tf(f)); }

__device__ __forceinline__ void mma8(float* d, const uint32_t* a, const uint32_t* b) {
    asm volatile(
        "mma.sync.aligned.m16n8k8.row.col.f32.tf32.tf32.f32 "
        "{%0,%1,%2,%3},{%4,%5,%6,%7},{%8,%9},{%0,%1,%2,%3};"
        : "+f"(d[0]), "+f"(d[1]), "+f"(d[2]), "+f"(d[3])
        : "r"(a[0]), "r"(a[1]), "r"(a[2]), "r"(a[3]), "r"(b[0]), "r"(b[1]));
}

__device__ __forceinline__ void cpa16(float* s, const float* g) {
    uint32_t sa = (uint32_t)__cvta_generic_to_shared(s);
    asm volatile("cp.async.cg.shared.global [%0], [%1], 16;" :: "r"(sa), "l"(g));
}

// ---------------------------------------------------------------------------
// gemm2 v3: C[128,128]-tiled  C = A[M,K] · B[N,K]^T  (both K-major, pre-rounded)
// 256 threads / 8 warps, warp tile 32x64 (4x2 warp grid), K-tile 32,
// 3-stage cp.async pipeline, 2 CTAs/SM (launch_bounds-capped regs).
// ---------------------------------------------------------------------------
#define G2_AST   36
#define G2_STG   (128 * G2_AST)
#define G2_SMEM  (6 * G2_STG * 4)      // 110592 bytes

template <bool RND>
__global__ __launch_bounds__(256, 2)
void gemm2(const float* __restrict__ A, const float* __restrict__ B,
           float* __restrict__ C, int lda, int ldb, int ldc, int K, int Hdim,
           long long sAb, long long sAh, long long sBb, long long sBh,
           long long sCb, long long sCh)
{
    extern __shared__ float sg[];
    float* const Asm = sg;
    float* const Bsm = sg + 3 * G2_STG;

    const int z = blockIdx.z;
    const int b = z / Hdim;
    const int h = z - b * Hdim;
    A += b * sAb + h * sAh;
    B += b * sBb + h * sBh;
    C += b * sCb + h * sCh;

    const int m0 = blockIdx.y * 128;
    const int n0 = blockIdx.x * 128;
    const int tid  = threadIdx.x;
    const int warp = tid >> 5;
    const int lane = tid & 31;
    const int lg = lane >> 2;
    const int lc = lane & 3;
    const int wR = (warp >> 1) * 32;   // 0,32,64,96
    const int wC = (warp & 1) * 64;    // 0,64

    float acc[2][8][4];
#pragma unroll
    for (int mt = 0; mt < 2; mt++)
#pragma unroll
        for (int nt = 0; nt < 8; nt++)
#pragma unroll
            for (int i = 0; i < 4; i++) acc[mt][nt][i] = 0.f;

    const int nc = K >> 5;

    auto loadStage = [&](int s, int c) {
        const int k0 = c << 5;
        float* as = Asm + s * G2_STG;
        float* bs = Bsm + s * G2_STG;
#pragma unroll
        for (int t = 0; t < 4; t++) {          // 128 rows x 8 chunks, 256 threads
            int idx = tid + t * 256;
            int r = idx >> 3, ch = (idx & 7) * 4;
            cpa16(&as[r * G2_AST + ch], A + (size_t)(m0 + r) * lda + k0 + ch);
            cpa16(&bs[r * G2_AST + ch], B + (size_t)(n0 + r) * ldb + k0 + ch);
        }
        asm volatile("cp.async.commit_group;");
    };

    loadStage(0, 0);
    if (nc > 1) loadStage(1, 1);

    for (int c = 0; c < nc; c++) {
        if (c + 1 < nc) asm volatile("cp.async.wait_group 1;");
        else            asm volatile("cp.async.wait_group 0;");
        __syncthreads();
        if (c + 2 < nc) loadStage((c + 2) % 3, c + 2);

        const float* as = Asm + (c % 3) * G2_STG;
        const float* bs = Bsm + (c % 3) * G2_STG;
#pragma unroll
        for (int koff = 0; koff < 32; koff += 8) {
            uint32_t af[2][4];
#pragma unroll
            for (int mt = 0; mt < 2; mt++) {
                const int r = wR + mt * 16 + lg;
                af[mt][0] = __float_as_uint(as[r * G2_AST + koff + lc]);
                af[mt][1] = __float_as_uint(as[(r + 8) * G2_AST + koff + lc]);
                af[mt][2] = __float_as_uint(as[r * G2_AST + koff + 4 + lc]);
                af[mt][3] = __float_as_uint(as[(r + 8) * G2_AST + koff + 4 + lc]);
            }
            uint32_t bf[8][2];
#pragma unroll
            for (int nt = 0; nt < 8; nt++) {
                const int cc = wC + nt * 8 + lg;
                bf[nt][0] = __float_as_uint(bs[cc * G2_AST + koff + lc]);
                bf[nt][1] = __float_as_uint(bs[cc * G2_AST + koff + 4 + lc]);
            }
#pragma unroll
            for (int mt = 0; mt < 2; mt++)
#pragma unroll
                for (int nt = 0; nt < 8; nt++)
                    mma8(acc[mt][nt], af[mt], bf[nt]);
        }
    }

#pragma unroll
    for (int mt = 0; mt < 2; mt++) {
        const int r = m0 + wR + mt * 16 + lg;
#pragma unroll
        for (int nt = 0; nt < 8; nt++) {
            const int cc = n0 + wC + nt * 8 + 2 * lc;
            float v0 = acc[mt][nt][0], v1 = acc[mt][nt][1];
            float v2 = acc[mt][nt][2], v3 = acc[mt][nt][3];
            if (RND) { v0 = rndf(v0); v1 = rndf(v1); v2 = rndf(v2); v3 = rndf(v3); }
            *reinterpret_cast<float2*>(&C[(size_t)r * ldc + cc])       = make_float2(v0, v1);
            *reinterpret_cast<float2*>(&C[(size_t)(r + 8) * ldc + cc]) = make_float2(v2, v3);
        }
    }
}

// ---------------------------------------------------------------------------
// Prep kernels
// ---------------------------------------------------------------------------
__global__ void round_concat(float* __restrict__ dst, const float* __restrict__ x,
                             const float* __restrict__ mem)
{
    int i = blockIdx.x * blockDim.x + threadIdx.x;
    if (i >= BB * TK * IN_DIM / 4) return;
    int row = i >> 8;
    int c4  = i & 255;
    int b = row >> 11, r = row & 2047;
    const float4* src = (r < 1024)
        ? reinterpret_cast<const float4*>(mem) + ((size_t)b * 1024 + r) * 256 + c4
        : reinterpret_cast<const float4*>(x)   + ((size_t)b * 1024 + (r - 1024)) * 256 + c4;
    float4 v = *src;
    v.x = rndf(v.x); v.y = rndf(v.y); v.z = rndf(v.z); v.w = rndf(v.w);
    reinterpret_cast<float4*>(dst)[i] = v;
}

// One launch for all three weight transposes.
__global__ void transpose_round_all(float* __restrict__ dqp, float* __restrict__ dkv,
                                    float* __restrict__ dwo,
                                    const float* __restrict__ Wq, const float* __restrict__ Wpos,
                                    const float* __restrict__ Wk, const float* __restrict__ Wv,
                                    const float* __restrict__ Wout)
{
    __shared__ float t[32][33];
    const int zz = blockIdx.z;
    float* dst;
    const float* s0;
    const float* s1;
    if (zz == 0)      { dst = dqp; s0 = Wq;   s1 = Wpos; }
    else if (zz == 1) { dst = dkv; s0 = Wk;   s1 = Wv;   }
    else              { dst = dwo; s0 = Wout; s1 = Wout; if (blockIdx.x >= 32) return; }

    const int n0 = blockIdx.x * 32;
    const int k0 = blockIdx.y * 32;
    const float* src = (n0 < 1024) ? s0 : s1;
    const int nn = (n0 < 1024) ? n0 : n0 - 1024;
    const int tx = threadIdx.x, ty = threadIdx.y;
#pragma unroll
    for (int i = 0; i < 32; i += 8)
        t[ty + i][tx] = rndf(src[(size_t)(k0 + ty + i) * 1024 + nn + tx]);
    __syncthreads();
#pragma unroll
    for (int i = 0; i < 32; i += 8)
        dst[(size_t)(n0 + ty + i) * 1024 + k0 + tx] = t[tx][ty + i];
}

// PB[b*16+h][n] = v2[h] . POS[b,n,h,:]
__global__ void pb_kernel(const float* __restrict__ QP, const float* __restrict__ v2,
                          float* __restrict__ PB)
{
    int idx = blockIdx.x * 256 + threadIdx.x;
    int z = idx >> 10, n = idx & 1023;
    int b = z >> 4, h = z & 15;
    const float* pos = QP + ((size_t)(b * TQ + n)) * LD2 + 1024 + h * DD;
    const float* vv  = v2 + h * DD;
    float s = 0.f;
#pragma unroll
    for (int k = 0; k < DD; k++) s += vv[k] * pos[k];
    PB[idx] = s;
}

// ---------------------------------------------------------------------------
// Flash attention (verbatim from passing R9/R10 kernel)
// ---------------------------------------------------------------------------
#define KSTR 68
#define VSTR 72
#define PSTR 132
#define SM_K0 0
#define SM_K1 (128 * KSTR)
#define SM_V0 (2 * 128 * KSTR)
#define SM_V1 (2 * 128 * KSTR + 128 * VSTR)
#define SM_P  (2 * 128 * KSTR + 2 * 128 * VSTR)
#define SM_TOT (SM_P + 128 * PSTR)
#define FLASH_SMEM (SM_TOT * 4)

__device__ __forceinline__ float posval(const float* __restrict__ Pr,
                                        const float* __restrict__ PBh, int q, int j) {
    if (j < 0 || j == q) return 0.f;
    int qq, cc;
    if (j < q) { qq = q;     cc = TQ + j - q; }
    else       { qq = q + 1; cc = j - q - 1;  }
    return __ldg(Pr + (size_t)qq * TQ + cc) + __ldg(PBh + cc);
}

__global__ __launch_bounds__(256, 1)
void flash_attn(const float* __restrict__ QP, const float* __restrict__ KV,
                const float* __restrict__ S2, const float* __restrict__ PB,
                const float* __restrict__ u, float* __restrict__ CTX)
{
    extern __shared__ float sm[];
    float* const Kbuf[2] = { sm + SM_K0, sm + SM_K1 };
    float* const Vbuf[2] = { sm + SM_V0, sm + SM_V1 };
    float* const Pb = sm + SM_P;

    const int q0 = blockIdx.x * 128;
    const int h  = blockIdx.y;
    const int b  = blockIdx.z;
    const int tid = threadIdx.x;
    const int w   = tid >> 5;
    const int lane = tid & 31;
    const int lg = lane >> 2;
    const int lc = lane & 3;

    const float* Qb = QP + ((size_t)b * TQ) * LD2 + h * DD;
    const float* Kb = KV + ((size_t)b * TK) * LD2 + h * DD;
    const float* Vb = Kb + 1024;
    const float* Pr = S2 + ((size_t)(b * HH + h)) * TQ * TQ;
    const float* PBh = PB + (size_t)(b * HH + h) * TQ;

#pragma unroll
    for (int i = 0; i < 8; i++) {
        int lin = tid + 256 * i;
        int r = lin >> 4, c4 = (lin & 15) * 4;
        float4 qv = *reinterpret_cast<const float4*>(Qb + (size_t)(q0 + r) * LD2 + c4);
        float4 uv = *reinterpret_cast<const float4*>(u + h * DD + c4);
        float* d = &Pb[r * PSTR + c4];
        d[0] = rndf(qv.x + uv.x); d[1] = rndf(qv.y + uv.y);
        d[2] = rndf(qv.z + uv.z); d[3] = rndf(qv.w + uv.w);
    }
    __syncthreads();

    uint32_t qf[8][4];
    {
        const int r0 = w * 16 + lg, r1 = r0 + 8;
#pragma unroll
        for (int s = 0; s < 8; s++) {
            qf[s][0] = __float_as_uint(Pb[r0 * PSTR + 8 * s + lc]);
            qf[s][1] = __float_as_uint(Pb[r1 * PSTR + 8 * s + lc]);
            qf[s][2] = __float_as_uint(Pb[r0 * PSTR + 8 * s + 4 + lc]);
            qf[s][3] = __float_as_uint(Pb[r1 * PSTR + 8 * s + 4 + lc]);
        }
    }
    __syncthreads();

    float Oa[8][4];
#pragma unroll
    for (int vt = 0; vt < 8; vt++)
#pragma unroll
        for (int i = 0; i < 4; i++) Oa[vt][i] = 0.f;
    float m0 = -3.0e38f, m1 = -3.0e38f, l0 = 0.f, l1 = 0.f;

    const int gq0 = q0 + w * 16 + lg;

    auto loadChunk = [&](int buf, int c) {
        const float* Kc = Kb + (size_t)c * 128 * LD2;
        const float* Vc = Vb + (size_t)c * 128 * LD2;
#pragma unroll
        for (int i = 0; i < 8; i++) {
            int lin = tid + 256 * i;
            int r = lin >> 4, c4 = (lin & 15) * 4;
            cpa16(&Kbuf[buf][r * KSTR + c4], Kc + (size_t)r * LD2 + c4);
            cpa16(&Vbuf[buf][r * VSTR + c4], Vc + (size_t)r * LD2 + c4);
        }
    };

    loadChunk(0, 0);
    asm volatile("cp.async.commit_group;");
    int buf = 0;

    for (int c = 0; c < 16; c++) {
        if (c < 15) {
            loadChunk(buf ^ 1, c + 1);
            asm volatile("cp.async.commit_group;");
            asm volatile("cp.async.wait_group 1;");
        } else {
            asm volatile("cp.async.wait_group 0;");
        }
        __syncthreads();

        float Sa[16][4];
#pragma unroll
        for (int nt = 0; nt < 16; nt++)
#pragma unroll
            for (int i = 0; i < 4; i++) Sa[nt][i] = 0.f;

        const float* Ks = Kbuf[buf];
        const int kbBase = lg * KSTR + lc;
#pragma unroll
        for (int s = 0; s < 8; s++) {
#pragma unroll
            for (int nt = 0; nt < 16; nt++) {
                uint32_t kb[2];
                kb[0] = __float_as_uint(Ks[kbBase + nt * 8 * KSTR + 8 * s]);
                kb[1] = __float_as_uint(Ks[kbBase + nt * 8 * KSTR + 8 * s + 4]);
                mma8(Sa[nt], qf[s], kb);
            }
        }

        const int kbase = c * 128;
        float rm0 = -3.0e38f, rm1 = -3.0e38f;
#pragma unroll
        for (int nt = 0; nt < 16; nt++) {
            if (kbase >= TMEMN) {
                const int kk0 = kbase + nt * 8 + 2 * lc;
                const int j0 = kk0 - TMEMN, j1 = j0 + 1;
                Sa[nt][0] += posval(Pr, PBh, gq0, j0);
                Sa[nt][1] += posval(Pr, PBh, gq0, j1);
                Sa[nt][2] += posval(Pr, PBh, gq0 + 8, j0);
                Sa[nt][3] += posval(Pr, PBh, gq0 + 8, j1);
            }
            Sa[nt][0] *= 0.125f; Sa[nt][1] *= 0.125f;
            Sa[nt][2] *= 0.125f; Sa[nt][3] *= 0.125f;
            rm0 = fmaxf(rm0, fmaxf(Sa[nt][0], Sa[nt][1]));
            rm1 = fmaxf(rm1, fmaxf(Sa[nt][2], Sa[nt][3]));
        }
        rm0 = fmaxf(rm0, __shfl_xor_sync(0xffffffffu, rm0, 1));
        rm0 = fmaxf(rm0, __shfl_xor_sync(0xffffffffu, rm0, 2));
        rm1 = fmaxf(rm1, __shfl_xor_sync(0xffffffffu, rm1, 1));
        rm1 = fmaxf(rm1, __shfl_xor_sync(0xffffffffu, rm1, 2));

        const float nm0 = fmaxf(m0, rm0), nm1 = fmaxf(m1, rm1);
        const float sc0 = __expf(m0 - nm0), sc1 = __expf(m1 - nm1);
        m0 = nm0; m1 = nm1;

        __syncwarp();
        float rs0 = 0.f, rs1 = 0.f;
        {
            float* p0row = &Pb[(w * 16 + lg) * PSTR];
            float* p1row = p0row + 8 * PSTR;
#pragma unroll
            for (int nt = 0; nt < 16; nt++) {
                float p0 = __expf(Sa[nt][0] - m0);
                float p1 = __expf(Sa[nt][1] - m0);
                float p2 = __expf(Sa[nt][2] - m1);
                float p3 = __expf(Sa[nt][3] - m1);
                rs0 += p0 + p1; rs1 += p2 + p3;
                *reinterpret_cast<float2*>(p0row + nt * 8 + 2 * lc) =
                    make_float2(rndf(p0), rndf(p1));
                *reinterpret_cast<float2*>(p1row + nt * 8 + 2 * lc) =
                    make_float2(rndf(p2), rndf(p3));
            }
        }
        rs0 += __shfl_xor_sync(0xffffffffu, rs0, 1);
        rs0 += __shfl_xor_sync(0xffffffffu, rs0, 2);
        rs1 += __shfl_xor_sync(0xffffffffu, rs1, 1);
        rs1 += __shfl_xor_sync(0xffffffffu, rs1, 2);
        l0 = l0 * sc0 + rs0;
        l1 = l1 * sc1 + rs1;
#pragma unroll
        for (int vt = 0; vt < 8; vt++) {
            Oa[vt][0] *= sc0; Oa[vt][1] *= sc0;
            Oa[vt][2] *= sc1; Oa[vt][3] *= sc1;
        }
        __syncwarp();

        const float* Vs = Vbuf[buf];
        const int pA0 = (w * 16 + lg) * PSTR + lc;
        const int pA1 = pA0 + 8 * PSTR;
#pragma unroll
        for (int s = 0; s < 16; s++) {
            uint32_t af[4];
            af[0] = __float_as_uint(Pb[pA0 + 8 * s]);
            af[1] = __float_as_uint(Pb[pA1 + 8 * s]);
            af[2] = __float_as_uint(Pb[pA0 + 8 * s + 4]);
            af[3] = __float_as_uint(Pb[pA1 + 8 * s + 4]);
            const int vb = (8 * s + lc) * VSTR + lg;
#pragma unroll
            for (int vt = 0; vt < 8; vt++) {
                uint32_t bv[2];
                bv[0] = __float_as_uint(Vs[vb + vt * 8]);
                bv[1] = __float_as_uint(Vs[vb + 4 * VSTR + vt * 8]);
                mma8(Oa[vt], af, bv);
            }
        }
        buf ^= 1;
        __syncthreads();
    }

    const float i0 = 1.f / l0, i1 = 1.f / l1;
    float* C0 = CTX + ((size_t)(b * TQ + gq0)) * HD + h * DD;
    float* C1 = C0 + 8 * HD;
#pragma unroll
    for (int vt = 0; vt < 8; vt++) {
        const int cc = vt * 8 + 2 * lc;
        *reinterpret_cast<float2*>(C0 + cc) =
            make_float2(rndf(Oa[vt][0] * i0), rndf(Oa[vt][1] * i0));
        *reinterpret_cast<float2*>(C1 + cc) =
            make_float2(rndf(Oa[vt][2] * i1), rndf(Oa[vt][3] * i1));
    }
}

// ---------------------------------------------------------------------------
// Host
// ---------------------------------------------------------------------------
extern "C" void kernel_launch(void* const* d_in, const int* in_sizes, int n_in,
                              void* d_out, int out_size)
{
    const float* x    = (const float*)d_in[0];
    const float* mem  = (const float*)d_in[1];
    // d_in[2] = attn_mask (identically True; unused)
    const float* Wq   = (const float*)d_in[3];
    const float* Wk   = (const float*)d_in[4];
    const float* Wv   = (const float*)d_in[5];
    const float* Wpos = (const float*)d_in[6];
    const float* u    = (const float*)d_in[7];
    const float* v2   = (const float*)d_in[8];
    const float* Wout = (const float*)d_in[9];
    float* out = (float*)d_out;

    float *pXM, *pWqpt, *pWkvt, *pWot, *pQP, *pKV, *pS2, *pPB, *pCTX;
    cudaGetSymbolAddress((void**)&pXM,   g_XM);
    cudaGetSymbolAddress((void**)&pWqpt, g_Wqpt);
    cudaGetSymbolAddress((void**)&pWkvt, g_Wkvt);
    cudaGetSymbolAddress((void**)&pWot,  g_Wot);
    cudaGetSymbolAddress((void**)&pQP,   g_QP);
    cudaGetSymbolAddress((void**)&pKV,   g_KV);
    cudaGetSymbolAddress((void**)&pS2,   g_S2);
    cudaGetSymbolAddress((void**)&pPB,   g_PB);
    cudaGetSymbolAddress((void**)&pCTX,  g_CTX);

    cudaFuncSetAttribute(flash_attn, cudaFuncAttributeMaxDynamicSharedMemorySize, FLASH_SMEM);
    cudaFuncSetAttribute(gemm2<true>,  cudaFuncAttributeMaxDynamicSharedMemorySize, G2_SMEM);
    cudaFuncSetAttribute(gemm2<false>, cudaFuncAttributeMaxDynamicSharedMemorySize, G2_SMEM);

    const long long sXMb = (long long)TK * IN_DIM;
    const long long sQPb = (long long)TQ * LD2;
    const long long sKVb = (long long)TK * LD2;

    // launch 0: input concat+round
    {
        int n4 = BB * TK * IN_DIM / 4;
        round_concat<<<(n4 + 255) / 256, 256>>>(pXM, x, mem);
    }
    // launch 1: all weight transposes
    transpose_round_all<<<dim3(64, 32, 3), dim3(32, 8)>>>(
        pWqpt, pWkvt, pWot, Wq, Wpos, Wk, Wv, Wout);

    // launches 2 & 3: projection GEMMs (profiler-steered slots)
    gemm2<true><<<dim3(16, 16, 2), 256, G2_SMEM>>>(
        pXM, pWkvt, pKV,
        IN_DIM, IN_DIM, LD2, IN_DIM, 1,
        sXMb, 0, 0, 0, sKVb, 0);
    gemm2<true><<<dim3(16, 8, 2), 256, G2_SMEM>>>(
        pXM + (size_t)TMEMN * IN_DIM, pWqpt, pQP,
        IN_DIM, IN_DIM, LD2, IN_DIM, 1,
        sXMb, 0, 0, 0, sQPb, 0);

    // S2 = Q · POS^T (per b,h; K=64)
    gemm2<false><<<dim3(8, 8, 32), 256, G2_SMEM>>>(
        pQP, pQP + 1024, pS2,
        LD2, LD2, TQ, DD, HH,
        sQPb, DD, sQPb, DD,
        (long long)HH * TQ * TQ, (long long)TQ * TQ);

    // PB = v2 · POS^T
    pb_kernel<<<128, 256>>>(pQP, v2, pPB);

    // flash attention
    flash_attn<<<dim3(8, 16, 2), 256, FLASH_SMEM>>>(pQP, pKV, pS2, pPB, u, pCTX);

    // OUT = CTX · Wout^T
    gemm2<false><<<dim3(8, 16, 1), 256, G2_SMEM>>>(
        pCTX, pWot, out,
        HD, HD, HD, HD, 1,
        0, 0, 0, 0, 0, 0);
}